// round 4
// baseline (speedup 1.0000x reference)
#include <cuda_runtime.h>
#include <cstdint>

#define S 64
#define P 2048
#define C 32
#define A 2048
#define D 128
#define E 64
#define E2 32

#define SPLITS 4
#define PH (P / SPLITS)      // 512
#define TILE 128
#define NT (PH / TILE)       // 4
#define G 2

typedef unsigned long long ull;

__device__ __forceinline__ ull pack2(float lo, float hi) {
    ull r; asm("mov.b64 %0,{%1,%2};" : "=l"(r) : "f"(lo), "f"(hi)); return r;
}
__device__ __forceinline__ void unpack2(ull v, float& lo, float& hi) {
    asm("mov.b64 {%0,%1},%2;" : "=f"(lo), "=f"(hi) : "l"(v));
}
__device__ __forceinline__ ull fma2(ull a, ull b, ull c) {
    ull d; asm("fma.rn.f32x2 %0,%1,%2,%3;" : "=l"(d) : "l"(a), "l"(b), "l"(c)); return d;
}
__device__ __forceinline__ ull add2(ull a, ull b) {
    ull d; asm("add.rn.f32x2 %0,%1,%2;" : "=l"(d) : "l"(a), "l"(b)); return d;
}
__device__ __forceinline__ ull mul2(ull a, ull b) {
    ull d; asm("mul.rn.f32x2 %0,%1,%2;" : "=l"(d) : "l"(a), "l"(b)); return d;
}
__device__ __forceinline__ ull relu2(ull v) {
    float lo, hi; unpack2(v, lo, hi);
    return pack2(fmaxf(lo, 0.f), fmaxf(hi, 0.f));
}

__device__ __forceinline__ uint32_t s2u(const void* p) {
    uint32_t a;
    asm("{ .reg .u64 t; cvta.to.shared.u64 t, %1; cvt.u32.u64 %0, t; }"
        : "=r"(a) : "l"(p));
    return a;
}
__device__ __forceinline__ void mbar_init(uint32_t mb, uint32_t cnt) {
    asm volatile("mbarrier.init.shared.b64 [%0], %1;" :: "r"(mb), "r"(cnt) : "memory");
}
__device__ __forceinline__ void mbar_expect(uint32_t mb, uint32_t bytes) {
    asm volatile("mbarrier.arrive.expect_tx.shared.b64 _, [%0], %1;"
                 :: "r"(mb), "r"(bytes) : "memory");
}
__device__ __forceinline__ void mbar_wait(uint32_t mb, uint32_t parity) {
    asm volatile(
        "{\n\t.reg .pred P;\n\t"
        "LW_%=:\n\t"
        "mbarrier.try_wait.parity.acquire.cta.shared::cta.b64 P, [%0], %1, 0x989680;\n\t"
        "@P bra LD_%=;\n\t"
        "bra LW_%=;\n\t"
        "LD_%=:\n\t}"
        :: "r"(mb), "r"(parity) : "memory");
}
__device__ __forceinline__ void bulk_g2s(uint32_t dst, const void* src,
                                         uint32_t bytes, uint32_t mb) {
    asm volatile(
        "cp.async.bulk.shared::cta.global.mbarrier::complete_tx::bytes [%0], [%1], %2, [%3];"
        :: "r"(dst), "l"(src), "r"(bytes), "r"(mb) : "memory");
}
__device__ __forceinline__ void fence_async_shared() {
    asm volatile("fence.proxy.async.shared::cta;" ::: "memory");
}

// ------------------------- global scratch -------------------------
__device__ float g_att1[S * P * E];          // [s][p][e], 33.5 MB (L2-resident)
__device__ ull   g_att2u[A * E2];
__device__ int   g_alist[S * A];
__device__ int   g_cnt[S];
__device__ float g_pm[A * SPLITS];
__device__ float g_pl[A * SPLITS];
__device__ ull   g_paccu[A * SPLITS * (C / 2)];

// ---------------------------------------------------------------------------
// per-scene agent lists (ballot compaction, deterministic)
// ---------------------------------------------------------------------------
__global__ __launch_bounds__(256) void k_group(const int* __restrict__ sidx) {
    int s = blockIdx.x, tid = threadIdx.x, wid = tid >> 5, lane = tid & 31;
    __shared__ int wcnt[8];
    int base = 0;
#pragma unroll
    for (int r = 0; r < A / 256; r++) {
        int a = r * 256 + tid;
        bool p = (sidx[a] == s);
        unsigned bal = __ballot_sync(0xffffffffu, p);
        if (lane == 0) wcnt[wid] = __popc(bal);
        __syncthreads();
        int woff = 0, tot = 0;
#pragma unroll
        for (int w = 0; w < 8; w++) { int c = wcnt[w]; if (w < wid) woff += c; tot += c; }
        if (p) g_alist[s * A + base + woff + __popc(bal & ((1u << lane) - 1u))] = a;
        base += tot;
        __syncthreads();
    }
    if (tid == 0) g_cnt[s] = base;
}

// ---------------------------------------------------------------------------
// att2[a] = b_df + dyn[a] @ W_df
// ---------------------------------------------------------------------------
__global__ __launch_bounds__(256) void k_att2(const float* __restrict__ dyn,
                                              const float* __restrict__ Wdf,
                                              const float* __restrict__ bdf) {
    __shared__ ull   Wp[D * E2];
    __shared__ float dyn_s[8 * D];
    int tid = threadIdx.x;
    int a0 = blockIdx.x * 8;
    const ull* Wsrc = (const ull*)Wdf;
    for (int i = tid; i < D * E2; i += 256) Wp[i] = Wsrc[i];
    ((float4*)dyn_s)[tid] = ((const float4*)(dyn + (size_t)a0 * D))[tid];
    __syncthreads();

    int aa = tid >> 5, e2 = tid & 31;
    ull acc = ((const ull*)bdf)[e2];
    const float* dr = dyn_s + aa * D;
#pragma unroll 8
    for (int c = 0; c < D; c++) {
        float d = dr[c];
        acc = fma2(pack2(d, d), Wp[c * E2 + e2], acc);
    }
    g_att2u[(size_t)(a0 + aa) * E2 + e2] = acc;
}

// ---------------------------------------------------------------------------
// att1[s,p,:] = b_sn + gs[s,p,:] @ W_sn  — coalesced out via smem staging.
// Block: 256 pixel-rows. stage row stride 66 floats (pad for banks).
// ---------------------------------------------------------------------------
#define A1_STRIDE 66
#define A1_SMEM (256 * A1_STRIDE * 4)
__global__ __launch_bounds__(256) void k_att1(const float* __restrict__ gs,
                                              const float* __restrict__ Wsn,
                                              const float* __restrict__ bsn) {
    extern __shared__ __align__(16) char smraw[];
    float* stage = (float*)smraw;
    __shared__ ull Wp[C * E2];
    __shared__ ull bp[E2];
    int tid = threadIdx.x;
    const ull* Wsrc = (const ull*)Wsn;
    for (int i = tid; i < C * E2; i += 256) Wp[i] = Wsrc[i];
    if (tid < E2) bp[tid] = ((const ull*)bsn)[tid];
    __syncthreads();

    size_t row = (size_t)blockIdx.x * 256 + tid;
    float g[C];
    const float4* gr = (const float4*)(gs + row * C);
#pragma unroll
    for (int j = 0; j < 8; j++) {
        float4 v = gr[j];
        g[4 * j] = v.x; g[4 * j + 1] = v.y; g[4 * j + 2] = v.z; g[4 * j + 3] = v.w;
    }
#pragma unroll
    for (int eh = 0; eh < 2; eh++) {
        ull acc[16];
#pragma unroll
        for (int k = 0; k < 16; k++) acc[k] = bp[eh * 16 + k];
#pragma unroll 4
        for (int c = 0; c < C; c++) {
            ull gg = pack2(g[c], g[c]);
#pragma unroll
            for (int k = 0; k < 16; k++)
                acc[k] = fma2(gg, Wp[c * E2 + eh * 16 + k], acc[k]);
        }
#pragma unroll
        for (int k = 0; k < 16; k++)
            *(ull*)(stage + tid * A1_STRIDE + eh * 32 + 2 * k) = acc[k];
    }
    __syncthreads();

    float2* dst = (float2*)(g_att1 + (size_t)blockIdx.x * 256 * E);
    for (int i = tid; i < 256 * 32; i += 256) {
        int px = i >> 5, j = i & 31;
        dst[i] = *(float2*)(stage + px * A1_STRIDE + j * 2);
    }
}

// ---------------------------------------------------------------------------
// k_attn — lane = agent, warp = 16-pixel slice, TMA double-buffered tiles.
// Block = (scene, quarter, group). b_fc dropped (softmax-invariant).
// ---------------------------------------------------------------------------
#define ATT1_TILE_B (TILE * E * 4)   // 32768
#define GS_TILE_B   (TILE * C * 4)   // 16384
#define STG_B       (ATT1_TILE_B + GS_TILE_B)  // 49152
#define OFF_STG0   0
#define OFF_STG1   49152
#define OFF_ATT2T  98304             // ull[32*32] = 8192
#define OFF_WFC    106496            // ull[32] = 256
#define OFF_MBAR   106752            // 2 × 8B
#define SMEM_ATTN  106880

__global__ __launch_bounds__(256) void k_attn(const float* __restrict__ gs,
                                              const float* __restrict__ wfc) {
    extern __shared__ __align__(16) char smraw[];
    ull* att2T = (ull*)(smraw + OFF_ATT2T);     // [e2][32 agents]
    ull* wfcp  = (ull*)(smraw + OFF_WFC);
    uint32_t stg[2] = { s2u(smraw + OFF_STG0), s2u(smraw + OFF_STG1) };
    uint32_t mb[2]  = { s2u(smraw + OFF_MBAR), s2u(smraw + OFF_MBAR + 8) };
    // combine area (reuses stage0 between tile phases)
    float* comb_m = (float*)(smraw);            // [256]
    float* comb_l = (float*)(smraw + 1024);     // [256]
    ull*   cacc   = (ull*)(smraw + 2048);       // [256][17] padded

    int tid = threadIdx.x, wid = tid >> 5, lane = tid & 31;
    int sblk = blockIdx.x >> 3;
    int quarter = (blockIdx.x >> 1) & 3;
    int grp = blockIdx.x & 1;

    const int nA = g_cnt[sblk];
    const int start = grp * 32;
    if (start >= nA) return;
    const int cend = (grp == 0) ? (nA < 32 ? nA : 32) : nA;
    const int p0 = quarter * PH;

    if (tid == 0) {
        mbar_init(mb[0], 1);
        mbar_init(mb[1], 1);
        fence_async_shared();
    }
    if (tid < E2) wfcp[tid] = ((const ull*)wfc)[tid];
    __syncthreads();

    const int* alist = g_alist + sblk * A;
    int uses[2] = {0, 0};
    const int pbase = wid * 16;

    for (int c0 = start; c0 < cend; c0 += 32) {
        const int end = (c0 + 32 < cend) ? c0 + 32 : cend;
        // stage att2 transposed [e2][slot]
        for (int idx = tid; idx < 32 * E2; idx += 256) {
            int j = idx & 31, e2 = idx >> 5;
            int src = c0 + j; if (src >= end) src = end - 1;
            att2T[e2 * 32 + j] = g_att2u[(size_t)alist[src] * E2 + e2];
        }
        if (tid == 0) {
#pragma unroll
            for (int k = 0; k < 2; k++) {
                size_t prow = (size_t)(sblk * P + p0 + k * TILE);
                mbar_expect(mb[k], STG_B);
                bulk_g2s(stg[k], g_att1 + prow * E, ATT1_TILE_B, mb[k]);
                bulk_g2s(stg[k] + ATT1_TILE_B, gs + prow * C, GS_TILE_B, mb[k]);
            }
        }
        __syncthreads();

        float m = -1e30f, l = 0.f;
        ull acc[16];
#pragma unroll
        for (int k = 0; k < 16; k++) acc[k] = 0ull;

        for (int t = 0; t < NT; t++) {
            const int b = t & 1;
            mbar_wait(mb[b], uses[b] & 1);
            uses[b]++;
            const ull* att1b = (const ull*)(smraw + (b ? OFF_STG1 : OFF_STG0));
            const ull* gsb = att1b + TILE * E2;   // [px][16 c-pairs]

            // logits for this warp's 16 pixels, all 32 lane-agents
            ull lg[16];
#pragma unroll
            for (int i = 0; i < 16; i++) lg[i] = 0ull;
            for (int e2 = 0; e2 < E2; e2++) {
                ull wv = wfcp[e2];
                ull bv = att2T[e2 * 32 + lane];
                const ull* a1 = att1b + pbase * E2 + e2;
#pragma unroll
                for (int i = 0; i < 16; i++) {
                    ull x = relu2(add2(a1[i * E2], bv));
                    lg[i] = fma2(x, wv, lg[i]);
                }
            }
            // tile softmax (lane-private, no shuffles)
            float ls[16];
#pragma unroll
            for (int i = 0; i < 16; i++) {
                float lo, hi; unpack2(lg[i], lo, hi);
                ls[i] = lo + hi;
            }
            float tm = ls[0];
#pragma unroll
            for (int i = 1; i < 16; i++) tm = fmaxf(tm, ls[i]);
            float mn = fmaxf(m, tm);
            float scale = __expf(m - mn);
            m = mn;
            l *= scale;
            ull sc2 = pack2(scale, scale);
#pragma unroll
            for (int k = 0; k < 16; k++) acc[k] = mul2(acc[k], sc2);
            // V accumulation
            for (int i = 0; i < 16; i++) {
                float w = __expf(ls[i] - mn);
                l += w;
                ull w2 = pack2(w, w);
                const ull* gr = gsb + (pbase + i) * 16;
#pragma unroll
                for (int k = 0; k < 16; k++)
                    acc[k] = fma2(w2, gr[k], acc[k]);
            }
            __syncthreads();   // all warps done with buffer b
            if (t + 2 < NT && tid == 0) {
                size_t prow = (size_t)(sblk * P + p0 + (t + 2) * TILE);
                mbar_expect(mb[b], STG_B);
                bulk_g2s(stg[b], g_att1 + prow * E, ATT1_TILE_B, mb[b]);
                bulk_g2s(stg[b] + ATT1_TILE_B, gs + prow * C, GS_TILE_B, mb[b]);
            }
        }

        // cross-warp combine (partials per lane-agent) via stage0 area
        {
            int off = wid * 32 + lane;
            comb_m[off] = m;
            comb_l[off] = l;
#pragma unroll
            for (int k = 0; k < 16; k++) cacc[off * 17 + k] = acc[k];
        }
        __syncthreads();
        if (wid == 0) {
            float M = m, L = l;
#pragma unroll 1
            for (int w = 1; w < 8; w++) {
                int off = w * 32 + lane;
                float m2 = comb_m[off], l2 = comb_l[off];
                float Mn = fmaxf(M, m2);
                float s1 = __expf(M - Mn), s2 = __expf(m2 - Mn);
                L = L * s1 + l2 * s2;
                ull s1v = pack2(s1, s1), s2v = pack2(s2, s2);
#pragma unroll
                for (int k = 0; k < 16; k++)
                    acc[k] = fma2(cacc[off * 17 + k], s2v, mul2(acc[k], s1v));
                M = Mn;
            }
            int idx = c0 + lane;
            if (idx < end) {
                int a = alist[idx];
                size_t slot = (size_t)a * SPLITS + quarter;
                g_pm[slot] = M;
                g_pl[slot] = L;
#pragma unroll
                for (int k = 0; k < 16; k++)
                    g_paccu[slot * 16 + k] = acc[k];
            }
        }
        __syncthreads();   // stage/att2T free for next chunk
    }
}

// ---------------------------------------------------------------------------
// combine SPLITS partial softmax states per agent
// ---------------------------------------------------------------------------
__global__ __launch_bounds__(256) void k_combine(float* __restrict__ out) {
    int gw = (blockIdx.x * blockDim.x + threadIdx.x) >> 5;
    int lane = threadIdx.x & 31;
    if (gw >= A) return;
    int a = gw;
    float mm[SPLITS], llv[SPLITS];
    float M = -1e30f;
#pragma unroll
    for (int k = 0; k < SPLITS; k++) {
        mm[k] = g_pm[a * SPLITS + k];
        llv[k] = g_pl[a * SPLITS + k];
        M = fmaxf(M, mm[k]);
    }
    const float* gp = (const float*)g_paccu;
    float L = 0.f, v = 0.f;
#pragma unroll
    for (int k = 0; k < SPLITS; k++) {
        float sk = __expf(mm[k] - M);
        L += llv[k] * sk;
        v += gp[(size_t)(a * SPLITS + k) * C + lane] * sk;
    }
    out[a * C + lane] = v / L;
}

// ---------------------------------------------------------------------------
extern "C" void kernel_launch(void* const* d_in, const int* in_sizes, int n_in,
                              void* d_out, int out_size) {
    const float* gs   = (const float*)d_in[0];
    const int*   sidx = (const int*)d_in[1];
    const float* dyn  = (const float*)d_in[2];
    const float* Wsn  = (const float*)d_in[3];
    const float* bsn  = (const float*)d_in[4];
    const float* Wdf  = (const float*)d_in[5];
    const float* bdf  = (const float*)d_in[6];
    const float* wfc  = (const float*)d_in[7];
    float* out = (float*)d_out;

    k_group<<<S, 256>>>(sidx);
    k_att2<<<A / 8, 256>>>(dyn, Wdf, bdf);

    cudaFuncSetAttribute(k_att1, cudaFuncAttributeMaxDynamicSharedMemorySize,
                         A1_SMEM);
    k_att1<<<(S * P) / 256, 256, A1_SMEM>>>(gs, Wsn, bsn);

    cudaFuncSetAttribute(k_attn, cudaFuncAttributeMaxDynamicSharedMemorySize,
                         SMEM_ATTN);
    k_attn<<<S * SPLITS * G, 256, SMEM_ATTN>>>(gs, wfc);

    k_combine<<<(A * 32) / 256, 256>>>(out);
}

// round 5
// speedup vs baseline: 1.0800x; 1.0800x over previous
#include <cuda_runtime.h>
#include <cstdint>

#define S 64
#define P 2048
#define C 32
#define A 2048
#define D 128
#define E 64
#define E2 32

#define SPLITS 8
#define PH (P / SPLITS)      // 256 pixels per block
#define GS_BYTES (PH * C * 4)  // 32768

typedef unsigned long long ull;

__device__ __forceinline__ ull pack2(float lo, float hi) {
    ull r; asm("mov.b64 %0,{%1,%2};" : "=l"(r) : "f"(lo), "f"(hi)); return r;
}
__device__ __forceinline__ void unpack2(ull v, float& lo, float& hi) {
    asm("mov.b64 {%0,%1},%2;" : "=f"(lo), "=f"(hi) : "l"(v));
}
__device__ __forceinline__ ull fma2(ull a, ull b, ull c) {
    ull d; asm("fma.rn.f32x2 %0,%1,%2,%3;" : "=l"(d) : "l"(a), "l"(b), "l"(c)); return d;
}
__device__ __forceinline__ ull add2(ull a, ull b) {
    ull d; asm("add.rn.f32x2 %0,%1,%2;" : "=l"(d) : "l"(a), "l"(b)); return d;
}
__device__ __forceinline__ ull mul2(ull a, ull b) {
    ull d; asm("mul.rn.f32x2 %0,%1,%2;" : "=l"(d) : "l"(a), "l"(b)); return d;
}
__device__ __forceinline__ ull relu2(ull v) {
    float lo, hi; unpack2(v, lo, hi);
    return pack2(fmaxf(lo, 0.f), fmaxf(hi, 0.f));
}
__device__ __forceinline__ uint32_t s2u(const void* p) {
    uint32_t a;
    asm("{ .reg .u64 t; cvta.to.shared.u64 t, %1; cvt.u32.u64 %0, t; }"
        : "=r"(a) : "l"(p));
    return a;
}
__device__ __forceinline__ void mbar_init(uint32_t mb, uint32_t cnt) {
    asm volatile("mbarrier.init.shared.b64 [%0], %1;" :: "r"(mb), "r"(cnt) : "memory");
}
__device__ __forceinline__ void mbar_expect(uint32_t mb, uint32_t bytes) {
    asm volatile("mbarrier.arrive.expect_tx.shared.b64 _, [%0], %1;"
                 :: "r"(mb), "r"(bytes) : "memory");
}
__device__ __forceinline__ void mbar_wait(uint32_t mb, uint32_t parity) {
    asm volatile(
        "{\n\t.reg .pred P;\n\t"
        "LW_%=:\n\t"
        "mbarrier.try_wait.parity.acquire.cta.shared::cta.b64 P, [%0], %1, 0x989680;\n\t"
        "@P bra LD_%=;\n\t"
        "bra LW_%=;\n\t"
        "LD_%=:\n\t}"
        :: "r"(mb), "r"(parity) : "memory");
}
__device__ __forceinline__ void bulk_g2s(uint32_t dst, const void* src,
                                         uint32_t bytes, uint32_t mb) {
    asm volatile(
        "cp.async.bulk.shared::cta.global.mbarrier::complete_tx::bytes [%0], [%1], %2, [%3];"
        :: "r"(dst), "l"(src), "r"(bytes), "r"(mb) : "memory");
}
__device__ __forceinline__ void fence_async_shared() {
    asm volatile("fence.proxy.async.shared::cta;" ::: "memory");
}

// ------------------------- global scratch -------------------------
__device__ ull   g_att2u[A * E2];
__device__ int   g_alist[S * A];
__device__ int   g_cnt[S];
__device__ float g_pm[A * SPLITS];
__device__ float g_pl[A * SPLITS];
__device__ ull   g_paccu[A * SPLITS * (C / 2)];

// ---------------------------------------------------------------------------
// per-scene agent lists (ballot compaction, deterministic)
// ---------------------------------------------------------------------------
__global__ __launch_bounds__(256) void k_group(const int* __restrict__ sidx) {
    int s = blockIdx.x, tid = threadIdx.x, wid = tid >> 5, lane = tid & 31;
    __shared__ int wcnt[8];
    int base = 0;
#pragma unroll
    for (int r = 0; r < A / 256; r++) {
        int a = r * 256 + tid;
        bool p = (sidx[a] == s);
        unsigned bal = __ballot_sync(0xffffffffu, p);
        if (lane == 0) wcnt[wid] = __popc(bal);
        __syncthreads();
        int woff = 0, tot = 0;
#pragma unroll
        for (int w = 0; w < 8; w++) { int c = wcnt[w]; if (w < wid) woff += c; tot += c; }
        if (p) g_alist[s * A + base + woff + __popc(bal & ((1u << lane) - 1u))] = a;
        base += tot;
        __syncthreads();
    }
    if (tid == 0) g_cnt[s] = base;
}

// ---------------------------------------------------------------------------
// att2[a] = b_df + dyn[a] @ W_df
// ---------------------------------------------------------------------------
__global__ __launch_bounds__(256) void k_att2(const float* __restrict__ dyn,
                                              const float* __restrict__ Wdf,
                                              const float* __restrict__ bdf) {
    __shared__ ull   Wp[D * E2];
    __shared__ float dyn_s[8 * D];
    int tid = threadIdx.x;
    int a0 = blockIdx.x * 8;
    const ull* Wsrc = (const ull*)Wdf;
    for (int i = tid; i < D * E2; i += 256) Wp[i] = Wsrc[i];
    ((float4*)dyn_s)[tid] = ((const float4*)(dyn + (size_t)a0 * D))[tid];
    __syncthreads();

    int aa = tid >> 5, e2 = tid & 31;
    ull acc = ((const ull*)bdf)[e2];
    const float* dr = dyn_s + aa * D;
#pragma unroll 8
    for (int c = 0; c < D; c++) {
        float d = dr[c];
        acc = fma2(pack2(d, d), Wp[c * E2 + e2], acc);
    }
    g_att2u[(size_t)(a0 + aa) * E2 + e2] = acc;
}

// ---------------------------------------------------------------------------
// k_attn — block = (scene, eighth of P). 512 threads / 16 warps.
// lane = agent (32-agent chunks), warp = 16-pixel slice of the 256 pixels.
// att1 computed in-block from global gs while the gs smem tile TMA-loads.
// b_fc dropped (softmax-invariant).
// ---------------------------------------------------------------------------
// smem layout (bytes, 16-aligned)
#define OFF_ATT1S 0                 // ull[256*33]      = 67584
#define OFF_GSS   67584             // ull[256*16]      = 32768
#define OFF_ATT2T 100352            // ull[32*32]       = 8192
#define OFF_WP    108544            // ull[32*32]       = 8192
#define OFF_MBUF  116736            // ull[8*17*32]     = 34816
#define OFF_WFC   151552            // ull[32]          = 256
#define OFF_BSN   151808            // ull[32]          = 256
#define OFF_MBAR  152064            // 8
#define SMEM_ATTN 152192

__global__ __launch_bounds__(512, 1) void k_attn(const float* __restrict__ gs,
                                                 const float* __restrict__ wfc,
                                                 const float* __restrict__ Wsn,
                                                 const float* __restrict__ bsn) {
    extern __shared__ __align__(16) char smraw[];
    ull* att1s = (ull*)(smraw + OFF_ATT1S);   // [px][33] (32 e-pairs + pad)
    ull* gss   = (ull*)(smraw + OFF_GSS);     // [px][16 c-pairs]
    ull* att2T = (ull*)(smraw + OFF_ATT2T);   // [e2][32 agent slots]
    ull* Wp    = (ull*)(smraw + OFF_WP);      // [c][32 e-pairs]
    ull* mbuf  = (ull*)(smraw + OFF_MBUF);    // [8][17][32]
    ull* wfcp  = (ull*)(smraw + OFF_WFC);
    ull* bsnp  = (ull*)(smraw + OFF_BSN);
    uint32_t mb = s2u(smraw + OFF_MBAR);

    const int tid = threadIdx.x, wid = tid >> 5, lane = tid & 31;
    const int sblk = blockIdx.x >> 3;
    const int eighth = blockIdx.x & 7;
    const int p0 = eighth * PH;
    const int nA = g_cnt[sblk];
    if (nA == 0) return;

    if (tid == 0) {
        mbar_init(mb, 1);
        fence_async_shared();
        mbar_expect(mb, GS_BYTES);
        bulk_g2s(s2u(gss), gs + (size_t)(sblk * P + p0) * C, GS_BYTES, mb);
    }
    // stage weights
    {
        const ull* Wsrc = (const ull*)Wsn;
        for (int i = tid; i < C * E2; i += 512) Wp[i] = Wsrc[i];
        if (tid < E2) {
            wfcp[tid] = ((const ull*)wfc)[tid];
            bsnp[tid] = ((const ull*)bsn)[tid];
        }
    }
    __syncthreads();   // Wp/bsnp visible (also mbar init visible to all)

    // fused att1: thread (px = tid>>1, half = tid&1) computes 16 e-pairs for
    // its pixel from GLOBAL gs (overlaps with the async gs->smem bulk copy).
    {
        const int px = tid >> 1, half = tid & 1;
        const float4* gr = (const float4*)(gs + (size_t)(sblk * P + p0 + px) * C);
        float g[32];
#pragma unroll
        for (int j = 0; j < 8; j++) {
            float4 v = gr[j];
            g[4 * j] = v.x; g[4 * j + 1] = v.y;
            g[4 * j + 2] = v.z; g[4 * j + 3] = v.w;
        }
        ull acc[16];
#pragma unroll
        for (int k = 0; k < 16; k++) acc[k] = bsnp[half * 16 + k];
#pragma unroll 4
        for (int c = 0; c < C; c++) {
            ull gg = pack2(g[c], g[c]);
#pragma unroll
            for (int k = 0; k < 16; k++)
                acc[k] = fma2(gg, Wp[c * E2 + half * 16 + k], acc[k]);
        }
        ull* dst = att1s + px * 33 + half * 16;
#pragma unroll
        for (int k = 0; k < 16; k++) dst[k] = acc[k];
    }
    mbar_wait(mb, 0);
    __syncthreads();   // att1s visible block-wide

    const int* alist = g_alist + sblk * A;
    const int pbase = wid * 16;

    for (int c0 = 0; c0 < nA; c0 += 32) {
        // stage att2 transposed [e2][slot] (clamped duplicates as padding)
        for (int idx = tid; idx < 32 * E2; idx += 512) {
            int j = idx & 31, e2 = idx >> 5;
            int src = c0 + j; if (src >= nA) src = nA - 1;
            att2T[e2 * 32 + j] = g_att2u[(size_t)alist[src] * E2 + e2];
        }
        __syncthreads();

        // logits: this warp's 16 pixels × 32 lane-agents, packed over e
        ull lg[16];
#pragma unroll
        for (int i = 0; i < 16; i++) lg[i] = 0ull;
#pragma unroll 2
        for (int e2 = 0; e2 < E2; e2++) {
            ull wv = wfcp[e2];
            ull bv = att2T[e2 * 32 + lane];
            const ull* a1 = att1s + pbase * 33 + e2;
#pragma unroll
            for (int i = 0; i < 16; i++)
                lg[i] = fma2(relu2(add2(a1[i * 33], bv)), wv, lg[i]);
        }
        // single-shot softmax over this warp's 16 pixels (lane-private)
        float ls[16];
#pragma unroll
        for (int i = 0; i < 16; i++) {
            float lo, hi; unpack2(lg[i], lo, hi);
            ls[i] = lo + hi;
        }
        float m = ls[0];
#pragma unroll
        for (int i = 1; i < 16; i++) m = fmaxf(m, ls[i]);
        float l = 0.f;
        ull acc[16];
#pragma unroll
        for (int k = 0; k < 16; k++) acc[k] = 0ull;
#pragma unroll
        for (int i = 0; i < 16; i++) {
            float w = __expf(ls[i] - m);
            l += w;
            ull w2 = pack2(w, w);
            const ull* grw = gss + (pbase + i) * 16;
#pragma unroll
            for (int k = 0; k < 16; k++)
                acc[k] = fma2(w2, grw[k], acc[k]);
        }

        // tree merge of 16 warp-states down to warp 0
        for (int r = 8; r >= 1; r >>= 1) {
            __syncthreads();
            if (wid >= r && wid < 2 * r) {
                ull* dst = mbuf + (size_t)(wid - r) * 17 * 32;
#pragma unroll
                for (int k = 0; k < 16; k++) dst[k * 32 + lane] = acc[k];
                dst[16 * 32 + lane] = pack2(m, l);
            }
            __syncthreads();
            if (wid < r) {
                const ull* src = mbuf + (size_t)wid * 17 * 32;
                float m2, l2; unpack2(src[16 * 32 + lane], m2, l2);
                float Mn = fmaxf(m, m2);
                float s1 = __expf(m - Mn), s2 = __expf(m2 - Mn);
                l = l * s1 + l2 * s2;
                ull s1v = pack2(s1, s1), s2v = pack2(s2, s2);
#pragma unroll
                for (int k = 0; k < 16; k++)
                    acc[k] = fma2(src[k * 32 + lane], s2v, mul2(acc[k], s1v));
                m = Mn;
            }
        }
        if (wid == 0) {
            int idx = c0 + lane;
            if (idx < nA) {
                int a = alist[idx];
                size_t slot = (size_t)a * SPLITS + eighth;
                g_pm[slot] = m;
                g_pl[slot] = l;
#pragma unroll
                for (int k = 0; k < 16; k++)
                    g_paccu[slot * 16 + k] = acc[k];
            }
        }
        __syncthreads();   // mbuf / att2T safe to reuse next chunk
    }
}

// ---------------------------------------------------------------------------
// combine SPLITS partial softmax states per agent
// ---------------------------------------------------------------------------
__global__ __launch_bounds__(256) void k_combine(float* __restrict__ out) {
    int gw = (blockIdx.x * blockDim.x + threadIdx.x) >> 5;
    int lane = threadIdx.x & 31;
    if (gw >= A) return;
    int a = gw;
    float mm[SPLITS], llv[SPLITS];
    float M = -1e30f;
#pragma unroll
    for (int k = 0; k < SPLITS; k++) {
        mm[k] = g_pm[a * SPLITS + k];
        llv[k] = g_pl[a * SPLITS + k];
        M = fmaxf(M, mm[k]);
    }
    const float* gp = (const float*)g_paccu;
    float L = 0.f, v = 0.f;
#pragma unroll
    for (int k = 0; k < SPLITS; k++) {
        float sk = __expf(mm[k] - M);
        L += llv[k] * sk;
        v += gp[(size_t)(a * SPLITS + k) * C + lane] * sk;
    }
    out[a * C + lane] = v / L;
}

// ---------------------------------------------------------------------------
extern "C" void kernel_launch(void* const* d_in, const int* in_sizes, int n_in,
                              void* d_out, int out_size) {
    const float* gs   = (const float*)d_in[0];
    const int*   sidx = (const int*)d_in[1];
    const float* dyn  = (const float*)d_in[2];
    const float* Wsn  = (const float*)d_in[3];
    const float* bsn  = (const float*)d_in[4];
    const float* Wdf  = (const float*)d_in[5];
    const float* bdf  = (const float*)d_in[6];
    const float* wfc  = (const float*)d_in[7];
    float* out = (float*)d_out;

    k_group<<<S, 256>>>(sidx);
    k_att2<<<A / 8, 256>>>(dyn, Wdf, bdf);

    cudaFuncSetAttribute(k_attn, cudaFuncAttributeMaxDynamicSharedMemorySize,
                         SMEM_ATTN);
    k_attn<<<S * SPLITS, 512, SMEM_ATTN>>>(gs, wfc, Wsn, bsn);

    k_combine<<<(A * 32) / 256, 256>>>(out);
}

// round 6
// speedup vs baseline: 1.1915x; 1.1033x over previous
#include <cuda_runtime.h>
#include <cstdint>

#define S 64
#define P 2048
#define C 32
#define A 2048
#define D 128
#define E 64
#define E2 32

#define SPLITS 16
#define PH (P / SPLITS)   // 128 pixels per block
#define NW 8              // warps per k_attn block

typedef unsigned long long ull;

__device__ __forceinline__ ull pack2(float lo, float hi) {
    ull r; asm("mov.b64 %0,{%1,%2};" : "=l"(r) : "f"(lo), "f"(hi)); return r;
}
__device__ __forceinline__ void unpack2(ull v, float& lo, float& hi) {
    asm("mov.b64 {%0,%1},%2;" : "=f"(lo), "=f"(hi) : "l"(v));
}
__device__ __forceinline__ ull fma2(ull a, ull b, ull c) {
    ull d; asm("fma.rn.f32x2 %0,%1,%2,%3;" : "=l"(d) : "l"(a), "l"(b), "l"(c)); return d;
}
__device__ __forceinline__ ull add2(ull a, ull b) {
    ull d; asm("add.rn.f32x2 %0,%1,%2;" : "=l"(d) : "l"(a), "l"(b)); return d;
}
__device__ __forceinline__ ull mul2(ull a, ull b) {
    ull d; asm("mul.rn.f32x2 %0,%1,%2;" : "=l"(d) : "l"(a), "l"(b)); return d;
}
__device__ __forceinline__ ull relu2(ull v) {
    float lo, hi; unpack2(v, lo, hi);
    return pack2(fmaxf(lo, 0.f), fmaxf(hi, 0.f));
}

// ------------------------- global scratch -------------------------
__device__ ull   g_att2u[A * E2];
__device__ int   g_alist[S * A];
__device__ int   g_cnt[S];
__device__ float g_pm[A * SPLITS];
__device__ float g_pl[A * SPLITS];
__device__ ull   g_paccu[A * SPLITS * (C / 2)];

// ---------------------------------------------------------------------------
// k_prep: blocks [0,S): per-scene agent lists (ballot compaction).
//         blocks [S, S+A/8): att2[a] = b_df + dyn[a] @ W_df (8 agents/block).
// ---------------------------------------------------------------------------
__global__ __launch_bounds__(256) void k_prep(const int* __restrict__ sidx,
                                              const float* __restrict__ dyn,
                                              const float* __restrict__ Wdf,
                                              const float* __restrict__ bdf) {
    __shared__ ull Wp2[D * E2];      // 32 KB (att2 role)
    __shared__ ull dyn2[8 * D];      // 8 KB pre-packed (d,d) pairs
    __shared__ int wcnt[8];          // group role

    const int tid = threadIdx.x, wid = tid >> 5, lane = tid & 31;

    if (blockIdx.x < S) {
        // ---- group role ----
        int s = blockIdx.x;
        int base = 0;
#pragma unroll
        for (int r = 0; r < A / 256; r++) {
            int a = r * 256 + tid;
            bool p = (sidx[a] == s);
            unsigned bal = __ballot_sync(0xffffffffu, p);
            if (lane == 0) wcnt[wid] = __popc(bal);
            __syncthreads();
            int woff = 0, tot = 0;
#pragma unroll
            for (int w = 0; w < 8; w++) {
                int c = wcnt[w]; if (w < wid) woff += c; tot += c;
            }
            if (p) g_alist[s * A + base + woff + __popc(bal & ((1u << lane) - 1u))] = a;
            base += tot;
            __syncthreads();
        }
        if (tid == 0) g_cnt[s] = base;
        return;
    }

    // ---- att2 role ----
    const int a0 = (blockIdx.x - S) * 8;
    const ull* Wsrc = (const ull*)Wdf;
    for (int i = tid; i < D * E2; i += 256) Wp2[i] = Wsrc[i];
    {
        float4 v = ((const float4*)(dyn + (size_t)a0 * D))[tid];
        dyn2[tid * 4 + 0] = pack2(v.x, v.x);
        dyn2[tid * 4 + 1] = pack2(v.y, v.y);
        dyn2[tid * 4 + 2] = pack2(v.z, v.z);
        dyn2[tid * 4 + 3] = pack2(v.w, v.w);
    }
    __syncthreads();

    const int aa = tid >> 5, e2 = tid & 31;
    ull acc0 = ((const ull*)bdf)[e2], acc1 = 0, acc2 = 0, acc3 = 0;
    const ull* dr = dyn2 + aa * D;
#pragma unroll 8
    for (int c = 0; c < D; c += 4) {
        acc0 = fma2(dr[c + 0], Wp2[(c + 0) * E2 + e2], acc0);
        acc1 = fma2(dr[c + 1], Wp2[(c + 1) * E2 + e2], acc1);
        acc2 = fma2(dr[c + 2], Wp2[(c + 2) * E2 + e2], acc2);
        acc3 = fma2(dr[c + 3], Wp2[(c + 3) * E2 + e2], acc3);
    }
    g_att2u[(size_t)(a0 + aa) * E2 + e2] = add2(add2(acc0, acc1), add2(acc2, acc3));
}

// ---------------------------------------------------------------------------
// k_attn — block = (scene, sixteenth of P). 256 threads / 8 warps.
// lane = agent (32-agent chunks), warp = 16-pixel slice of the 128 pixels.
// att1 computed in-block; gs tile written to smem from the same registers.
// b_fc dropped (softmax-invariant).
// ---------------------------------------------------------------------------
// smem layout (ull offsets via byte offsets, all 16B-aligned)
#define OFF_ATT1S 0                  // ull[128*34] = 34816
#define OFF_GSS   34816              // ull[128*16] = 16384
#define OFF_ATT2T 51200              // ull[32*33]  = 8448 -> pad to 8464
#define OFF_WP    59664              // ull[32*32]  = 8192
#define OFF_MBUF  67856              // ull[4*17*32]= 17408
#define OFF_WFC   85264              // ull[32]     = 256
#define OFF_BSN   85520              // ull[32]     = 256
#define SMEM_ATTN 85776

__global__ __launch_bounds__(256, 2) void k_attn(const float* __restrict__ gs,
                                                 const float* __restrict__ wfc,
                                                 const float* __restrict__ Wsn,
                                                 const float* __restrict__ bsn) {
    extern __shared__ __align__(16) char smraw[];
    ull* att1s = (ull*)(smraw + OFF_ATT1S);   // [px][34] (32 e-pairs + pad)
    ull* gss   = (ull*)(smraw + OFF_GSS);     // [px][16 c-pairs]
    ull* att2T = (ull*)(smraw + OFF_ATT2T);   // [e2][33] (32 slots + pad)
    ull* Wp    = (ull*)(smraw + OFF_WP);      // [c][32 e-pairs]
    ull* mbuf  = (ull*)(smraw + OFF_MBUF);    // [4][17][32]
    ull* wfcp  = (ull*)(smraw + OFF_WFC);
    ull* bsnp  = (ull*)(smraw + OFF_BSN);

    const int tid = threadIdx.x, wid = tid >> 5, lane = tid & 31;
    const int sblk = blockIdx.x >> 4;
    const int part = blockIdx.x & 15;
    const int p0 = part * PH;
    const int nA = g_cnt[sblk];
    if (nA == 0) return;

    // stage weights
    {
        const ull* Wsrc = (const ull*)Wsn;
        for (int i = tid; i < C * E2; i += 256) Wp[i] = Wsrc[i];
        if (tid < E2) {
            wfcp[tid] = ((const ull*)wfc)[tid];
            bsnp[tid] = ((const ull*)bsn)[tid];
        }
    }
    __syncthreads();

    // prologue: compute att1 for this block's 128 pixels; also write gss.
    // thread pair (px = tid>>1, half = tid&1): each computes 16 e-pairs.
    {
        const int px = tid >> 1, half = tid & 1;
        const float4* gr = (const float4*)(gs + (size_t)(sblk * P + p0 + px) * C);
        float g[32]; ull gu[16];
#pragma unroll
        for (int j = 0; j < 8; j++) {
            float4 v = gr[j];
            g[4 * j] = v.x; g[4 * j + 1] = v.y;
            g[4 * j + 2] = v.z; g[4 * j + 3] = v.w;
            gu[2 * j] = pack2(v.x, v.y);
            gu[2 * j + 1] = pack2(v.z, v.w);
        }
        ull acc[16];
#pragma unroll
        for (int k = 0; k < 16; k++) acc[k] = bsnp[half * 16 + k];
#pragma unroll 4
        for (int c = 0; c < C; c++) {
            ull gg = pack2(g[c], g[c]);
#pragma unroll
            for (int k = 0; k < 16; k++)
                acc[k] = fma2(gg, Wp[c * E2 + half * 16 + k], acc[k]);
        }
        ulonglong2* dst = (ulonglong2*)(att1s + px * 34 + half * 16);
#pragma unroll
        for (int k = 0; k < 8; k++) {
            ulonglong2 v2; v2.x = acc[2 * k]; v2.y = acc[2 * k + 1];
            dst[k] = v2;
        }
        if (half == 0) {
            ulonglong2* gd = (ulonglong2*)(gss + px * 16);
#pragma unroll
            for (int k = 0; k < 8; k++) {
                ulonglong2 v2; v2.x = gu[2 * k]; v2.y = gu[2 * k + 1];
                gd[k] = v2;
            }
        }
    }
    __syncthreads();

    const int* alist = g_alist + sblk * A;
    const int pbase = wid * 16;

    for (int c0 = 0; c0 < nA; c0 += 32) {
        // stage att2 transposed [e2][slot]; coalesced LDG, conflict-free STS
        for (int idx = tid; idx < 32 * E2; idx += 256) {
            int j = idx >> 5, e2 = idx & 31;
            int src = c0 + j; if (src >= nA) src = nA - 1;
            att2T[e2 * 33 + j] = g_att2u[(size_t)alist[src] * E2 + e2];
        }
        __syncthreads();

        // logits: 16 pixels (this warp) x 32 lane-agents, e packed+paired
        ull lg[16];
#pragma unroll
        for (int i = 0; i < 16; i++) lg[i] = 0ull;
#pragma unroll 2
        for (int e2 = 0; e2 < E2; e2 += 2) {
            ull wv0 = wfcp[e2], wv1 = wfcp[e2 + 1];
            ull bv0 = att2T[e2 * 33 + lane], bv1 = att2T[(e2 + 1) * 33 + lane];
            const ulonglong2* a1 = (const ulonglong2*)(att1s + pbase * 34 + e2);
#pragma unroll
            for (int i = 0; i < 16; i++) {
                ulonglong2 av = a1[i * 17];
                lg[i] = fma2(relu2(add2(av.x, bv0)), wv0, lg[i]);
                lg[i] = fma2(relu2(add2(av.y, bv1)), wv1, lg[i]);
            }
        }
        // single-shot softmax over this warp's 16 pixels (lane-private)
        float ls[16];
#pragma unroll
        for (int i = 0; i < 16; i++) {
            float lo, hi; unpack2(lg[i], lo, hi);
            ls[i] = lo + hi;
        }
        float t8[8];
#pragma unroll
        for (int i = 0; i < 8; i++) t8[i] = fmaxf(ls[i], ls[i + 8]);
        float t4a = fmaxf(t8[0], t8[4]), t4b = fmaxf(t8[1], t8[5]);
        float t4c = fmaxf(t8[2], t8[6]), t4d = fmaxf(t8[3], t8[7]);
        float m = fmaxf(fmaxf(t4a, t4b), fmaxf(t4c, t4d));

        float l0 = 0.f, l1 = 0.f;
        ull acc[16];
#pragma unroll
        for (int k = 0; k < 16; k++) acc[k] = 0ull;
#pragma unroll 4
        for (int i = 0; i < 16; i++) {
            float w = __expf(ls[i] - m);
            if (i & 1) l1 += w; else l0 += w;
            ull w2 = pack2(w, w);
            const ulonglong2* grw = (const ulonglong2*)(gss + (pbase + i) * 16);
#pragma unroll
            for (int k = 0; k < 8; k++) {
                ulonglong2 gv = grw[k];
                acc[2 * k]     = fma2(w2, gv.x, acc[2 * k]);
                acc[2 * k + 1] = fma2(w2, gv.y, acc[2 * k + 1]);
            }
        }
        float l = l0 + l1;

        // tree merge of 8 warp-states down to warp 0
        for (int r = 4; r >= 1; r >>= 1) {
            __syncthreads();
            if (wid >= r && wid < 2 * r) {
                ull* dst = mbuf + (size_t)(wid - r) * 17 * 32;
#pragma unroll
                for (int k = 0; k < 16; k++) dst[k * 32 + lane] = acc[k];
                dst[16 * 32 + lane] = pack2(m, l);
            }
            __syncthreads();
            if (wid < r) {
                const ull* src = mbuf + (size_t)wid * 17 * 32;
                float m2, l2; unpack2(src[16 * 32 + lane], m2, l2);
                float Mn = fmaxf(m, m2);
                float s1 = __expf(m - Mn), s2 = __expf(m2 - Mn);
                l = l * s1 + l2 * s2;
                ull s1v = pack2(s1, s1), s2v = pack2(s2, s2);
#pragma unroll
                for (int k = 0; k < 16; k++)
                    acc[k] = fma2(src[k * 32 + lane], s2v, mul2(acc[k], s1v));
                m = Mn;
            }
        }
        if (wid == 0) {
            int idx = c0 + lane;
            if (idx < nA) {
                int a = alist[idx];
                size_t slot = (size_t)a * SPLITS + part;
                g_pm[slot] = m;
                g_pl[slot] = l;
#pragma unroll
                for (int k = 0; k < 16; k++)
                    g_paccu[slot * 16 + k] = acc[k];
            }
        }
        __syncthreads();   // mbuf / att2T safe for next chunk
    }
}

// ---------------------------------------------------------------------------
// combine SPLITS partial softmax states per agent
// ---------------------------------------------------------------------------
__global__ __launch_bounds__(256) void k_combine(float* __restrict__ out) {
    int gw = (blockIdx.x * blockDim.x + threadIdx.x) >> 5;
    int lane = threadIdx.x & 31;
    if (gw >= A) return;
    int a = gw;
    float mm[SPLITS], llv[SPLITS];
    float M = -1e30f;
#pragma unroll
    for (int k = 0; k < SPLITS; k++) {
        mm[k] = g_pm[a * SPLITS + k];
        llv[k] = g_pl[a * SPLITS + k];
        M = fmaxf(M, mm[k]);
    }
    const float* gp = (const float*)g_paccu;
    float L = 0.f, v = 0.f;
#pragma unroll
    for (int k = 0; k < SPLITS; k++) {
        float sk = __expf(mm[k] - M);
        L += llv[k] * sk;
        v += gp[(size_t)(a * SPLITS + k) * C + lane] * sk;
    }
    out[a * C + lane] = v / L;
}

// ---------------------------------------------------------------------------
extern "C" void kernel_launch(void* const* d_in, const int* in_sizes, int n_in,
                              void* d_out, int out_size) {
    const float* gs   = (const float*)d_in[0];
    const int*   sidx = (const int*)d_in[1];
    const float* dyn  = (const float*)d_in[2];
    const float* Wsn  = (const float*)d_in[3];
    const float* bsn  = (const float*)d_in[4];
    const float* Wdf  = (const float*)d_in[5];
    const float* bdf  = (const float*)d_in[6];
    const float* wfc  = (const float*)d_in[7];
    float* out = (float*)d_out;

    k_prep<<<S + A / 8, 256>>>(sidx, dyn, Wdf, bdf);

    cudaFuncSetAttribute(k_attn, cudaFuncAttributeMaxDynamicSharedMemorySize,
                         SMEM_ATTN);
    k_attn<<<S * SPLITS, 256, SMEM_ATTN>>>(gs, wfc, Wsn, bsn);

    k_combine<<<(A * 32) / 256, 256>>>(out);
}